// round 3
// baseline (speedup 1.0000x reference)
#include <cuda_runtime.h>
#include <cstdint>

// Problem constants
#define BATCH     64
#define NPER      786432
#define VPER      (NPER / 4)              // 196608 int4 per row
#define LEVELS    256
#define HTHREADS  128                     // 4 warps
#define BPR       16                      // blocks per row -> grid 1024
#define V_PER_CTA (VPER / BPR)            // 12288 int4
#define ITERS     (V_PER_CTA / HTHREADS)  // 96 int4 per thread (384 elements)

// Per-(row, block) partial histograms: pure overwrite each call (no zeroing).
__device__ unsigned int g_part[BATCH * BPR * LEVELS];   // 1 MB

// ---------------------------------------------------------------------------
// Kernel 1: per-row histogram, FULLY THREAD-PRIVATE packed-u8 smem counters.
// Layout sh[warp][word][lane]: word = bin>>2, byte = bin&3, bank = lane.
// No atomics: plain LDS/IADD/STS; no races (privacy), no conflicts (bank=lane).
// ---------------------------------------------------------------------------
__global__ __launch_bounds__(HTHREADS)
void hist_kernel(const int4* __restrict__ x) {
    __shared__ unsigned int sh[4 * 64 * 32];   // 32 KB

    #pragma unroll
    for (int i = threadIdx.x; i < 4 * 64 * 32; i += HTHREADS) sh[i] = 0u;
    __syncthreads();

    const unsigned tid  = threadIdx.x;
    const unsigned lane = tid & 31u;
    const unsigned warp = tid >> 5;
    unsigned int* __restrict__ myh = sh + warp * (64 * 32) + lane;

    const int b = blockIdx.y;
    const int4* __restrict__ blk =
        x + (size_t)b * VPER + (size_t)blockIdx.x * V_PER_CTA;

    #pragma unroll 4
    for (int it = 0; it < ITERS; it++) {
        int4 v = blk[it * HTHREADS + tid];
        myh[((unsigned)v.x >> 2) * 32] += 1u << (((unsigned)v.x & 3u) << 3);
        myh[((unsigned)v.y >> 2) * 32] += 1u << (((unsigned)v.y & 3u) << 3);
        myh[((unsigned)v.z >> 2) * 32] += 1u << (((unsigned)v.z & 3u) << 3);
        myh[((unsigned)v.w >> 2) * 32] += 1u << (((unsigned)v.w & 3u) << 3);
    }
    __syncthreads();

    // Reduce 128 (warp,lane) copies. Thread t owns bins 2t and 2t+1 (same word
    // index t>>1). dp4a with a one-hot byte selector extracts the u8 field.
    const unsigned wordIdx = tid >> 1;
    const unsigned sel0 = 1u << (((2u * tid) & 3u) << 3);
    const unsigned sel1 = sel0 << 8;

    unsigned s0 = 0, s1 = 0;
    #pragma unroll 8
    for (int c = 0; c < 128; c++) {
        unsigned idx = (c + tid) & 127u;         // rotate: bank = idx&31 distinct
        unsigned w = idx >> 5, l = idx & 31u;
        unsigned val = sh[w * (64 * 32) + wordIdx * 32 + l];
        s0 = __dp4a(val, sel0, s0);
        s1 = __dp4a(val, sel1, s1);
    }

    unsigned base = ((unsigned)b * BPR + blockIdx.x) * LEVELS;
    g_part[base + 2 * tid]     = s0;
    g_part[base + 2 * tid + 1] = s1;
}

// ---------------------------------------------------------------------------
// Kernel 2: sum BPR partials per (row, bin), broadcast across 256 columns.
// grid = (16, BATCH): block g covers bins [g*16, g*16+16) of row b.
// 1024 CTAs x 16 KB output each -> good launch parallelism.
// ---------------------------------------------------------------------------
__global__ __launch_bounds__(HTHREADS)
void bcast_kernel(float4* __restrict__ out) {
    __shared__ float sh[16];

    const int b = blockIdx.y;
    const int g = blockIdx.x;
    const int tid = threadIdx.x;

    // 16 bins x 16 partials = 256 values; 128 threads load 2 each.
    const int p   = tid & 15;          // partial index
    const int bl0 = tid >> 4;          // local bin 0..7 (and +8)
    const unsigned* __restrict__ gp =
        g_part + ((unsigned)b * BPR + p) * LEVELS + g * 16;
    unsigned s0 = gp[bl0];
    unsigned s1 = gp[bl0 + 8];
    #pragma unroll
    for (int o = 8; o; o >>= 1) {
        s0 += __shfl_xor_sync(0xFFFFFFFFu, s0, o);
        s1 += __shfl_xor_sync(0xFFFFFFFFu, s1, o);
    }
    if (p == 0) { sh[bl0] = (float)s0; sh[bl0 + 8] = (float)s1; }
    __syncthreads();

    // 16 bins x 64 float4 = 1024 float4; 8 per thread, coalesced.
    float4* __restrict__ dst =
        out + ((size_t)b * LEVELS + (size_t)g * 16) * (LEVELS / 4);
    #pragma unroll
    for (int i = tid; i < 16 * (LEVELS / 4); i += HTHREADS) {
        float v = sh[i >> 6];
        dst[i] = make_float4(v, v, v, v);
    }
}

// ---------------------------------------------------------------------------
extern "C" void kernel_launch(void* const* d_in, const int* in_sizes, int n_in,
                              void* d_out, int out_size) {
    const int4* x = (const int4*)d_in[0];
    float4* out = (float4*)d_out;

    dim3 hgrid(BPR, BATCH);
    hist_kernel<<<hgrid, HTHREADS>>>(x);

    dim3 bgrid(16, BATCH);
    bcast_kernel<<<bgrid, HTHREADS>>>(out);
}

// round 4
// speedup vs baseline: 1.5716x; 1.5716x over previous
#include <cuda_runtime.h>
#include <cstdint>

// Problem constants
#define BATCH     64
#define NPER      786432
#define VPER      (NPER / 4)              // 196608 int4 per row
#define LEVELS    256
#define HTHREADS  256
#define BPR       16                      // hist blocks per row -> 1024 CTAs
#define V_PER_CTA (VPER / BPR)            // 12288 int4
#define ITERS     (V_PER_CTA / HTHREADS)  // 48 int4 per thread

// Final per-row histograms. Statically zero-initialized; each bcast warp
// re-zeroes its entry after reading, so every graph replay starts from zeros.
__device__ unsigned int g_hist[BATCH * LEVELS];   // 64 KB

// ---------------------------------------------------------------------------
// Kernel 1: per-row histogram (round-2 proven mainloop).
// Lane-private smem counter copies: sh[v*32 + lane] -> bank == lane, zero
// conflicts; inter-warp races on (v,lane) handled by red.shared (no return,
// no dependent chain). Tail: reduce 32 copies, one global RED per bin.
// ---------------------------------------------------------------------------
__global__ __launch_bounds__(HTHREADS)
void hist_kernel(const int4* __restrict__ x) {
    __shared__ unsigned int sh[LEVELS * 32];   // 32 KB

    #pragma unroll
    for (int i = threadIdx.x; i < LEVELS * 32; i += HTHREADS) sh[i] = 0u;
    __syncthreads();

    const unsigned lane = threadIdx.x & 31u;
    unsigned int hbase = (unsigned int)__cvta_generic_to_shared(sh) + (lane << 2);

    const int b = blockIdx.y;
    const int4* __restrict__ blk =
        x + (size_t)b * VPER + (size_t)blockIdx.x * V_PER_CTA;

    #pragma unroll 4
    for (int it = 0; it < ITERS; it++) {
        int4 v = blk[it * HTHREADS + threadIdx.x];
        asm volatile("red.shared.add.u32 [%0], %1;"
                     :: "r"(hbase + ((unsigned)v.x << 7)), "r"(1u) : "memory");
        asm volatile("red.shared.add.u32 [%0], %1;"
                     :: "r"(hbase + ((unsigned)v.y << 7)), "r"(1u) : "memory");
        asm volatile("red.shared.add.u32 [%0], %1;"
                     :: "r"(hbase + ((unsigned)v.z << 7)), "r"(1u) : "memory");
        asm volatile("red.shared.add.u32 [%0], %1;"
                     :: "r"(hbase + ((unsigned)v.w << 7)), "r"(1u) : "memory");
    }
    __syncthreads();

    // Reduce the 32 lane-copies of bin t (rotated start -> conflict-free),
    // then one spread-address global RED per bin.
    const unsigned t = threadIdx.x;
    unsigned int s = 0;
    #pragma unroll
    for (int c = 0; c < 32; c++) s += sh[t * 32 + ((c + t) & 31u)];

    atomicAdd(&g_hist[(unsigned)b * LEVELS + t], s);   // RED.E.ADD (no return)
}

// ---------------------------------------------------------------------------
// Kernel 2: one warp per (row, bin). lane0 reads the count, shfl-broadcast,
// every lane stores 2 coalesced float4 (64 float4 = 256 floats per bin).
// lane0 zeroes the g_hist entry AFTER the read (sole reader -> race-free),
// so the next graph replay accumulates onto zeros without a zero kernel.
// ---------------------------------------------------------------------------
__global__ __launch_bounds__(256)
void bcast_kernel(float4* __restrict__ out) {
    const unsigned gtid = blockIdx.x * 256u + threadIdx.x;
    const unsigned w    = gtid >> 5;          // global warp id = b*256 + l
    const unsigned lane = threadIdx.x & 31u;

    unsigned cnt = 0;
    if (lane == 0) cnt = g_hist[w];
    cnt = __shfl_sync(0xFFFFFFFFu, cnt, 0);

    float v = (float)cnt;
    float4 f = make_float4(v, v, v, v);
    float4* __restrict__ dst = out + (size_t)w * (LEVELS / 4);
    dst[lane]      = f;
    dst[lane + 32] = f;

    if (lane == 0) g_hist[w] = 0u;            // reset for next replay
}

// ---------------------------------------------------------------------------
extern "C" void kernel_launch(void* const* d_in, const int* in_sizes, int n_in,
                              void* d_out, int out_size) {
    const int4* x = (const int4*)d_in[0];
    float4* out = (float4*)d_out;

    dim3 hgrid(BPR, BATCH);
    hist_kernel<<<hgrid, HTHREADS>>>(x);

    // 64*256 bins, one warp each -> 16384 warps -> 2048 CTAs of 256 threads
    bcast_kernel<<<(BATCH * LEVELS) / 8, 256>>>(out);
}

// round 5
// speedup vs baseline: 1.7184x; 1.0934x over previous
#include <cuda_runtime.h>
#include <cstdint>

// Problem constants
#define BATCH     64
#define NPER      786432
#define VPER      (NPER / 4)              // 196608 int4 per row
#define LEVELS    256
#define HTHREADS  256
#define BPR       8                       // hist CTAs per row -> 512 CTAs total
#define V_PER_CTA (VPER / BPR)            // 24576 int4
#define ITERS     (V_PER_CTA / HTHREADS)  // 96 int4 per thread

// All statically zero; every launch returns them to zero -> graph-replay safe.
__device__ unsigned int g_hist[BATCH * LEVELS];   // per-row histograms
__device__ unsigned int g_cnt[BATCH];             // arrival tickets per row
__device__ unsigned int g_flag[BATCH];            // row-complete flag
__device__ unsigned int g_done[BATCH];            // broadcast-done tickets

// ---------------------------------------------------------------------------
// Single fused kernel. grid = (BPR, BATCH), 256 threads.
// __launch_bounds__(256, 4) guarantees >=4 CTAs/SM resident (regs<=64,
// smem 32KB -> 7/SM, threads -> 8/SM), so all 512 CTAs are one co-resident
// wave and the cross-CTA spin below cannot deadlock.
//
// Phase 1 (hist): lane-private smem counter copies sh[v*32+lane] (bank==lane,
//   conflict-free), red.shared increments (no return, no dependent chain),
//   reduce 32 copies, one global RED per bin into g_hist.
// Phase 2 (sync): per-row ticket; last CTA of the row raises g_flag[b].
// Phase 3 (bcast): CTA i of row b broadcasts bins [i*32, i*32+32) to out,
//   zeroes its own g_hist entries; last CTA to finish resets the row counters.
// ---------------------------------------------------------------------------
__global__ void __launch_bounds__(HTHREADS, 4)
fused_kernel(const int4* __restrict__ x, float4* __restrict__ out) {
    __shared__ unsigned int sh[LEVELS * 32];   // 32 KB

    #pragma unroll
    for (int i = threadIdx.x; i < LEVELS * 32; i += HTHREADS) sh[i] = 0u;
    __syncthreads();

    const unsigned lane = threadIdx.x & 31u;
    unsigned int hbase = (unsigned int)__cvta_generic_to_shared(sh) + (lane << 2);

    const int b = blockIdx.y;
    const int i = blockIdx.x;
    const int4* __restrict__ blk =
        x + (size_t)b * VPER + (size_t)i * V_PER_CTA;

    #pragma unroll 4
    for (int it = 0; it < ITERS; it++) {
        int4 v = blk[it * HTHREADS + threadIdx.x];
        asm volatile("red.shared.add.u32 [%0], %1;"
                     :: "r"(hbase + ((unsigned)v.x << 7)), "r"(1u) : "memory");
        asm volatile("red.shared.add.u32 [%0], %1;"
                     :: "r"(hbase + ((unsigned)v.y << 7)), "r"(1u) : "memory");
        asm volatile("red.shared.add.u32 [%0], %1;"
                     :: "r"(hbase + ((unsigned)v.z << 7)), "r"(1u) : "memory");
        asm volatile("red.shared.add.u32 [%0], %1;"
                     :: "r"(hbase + ((unsigned)v.w << 7)), "r"(1u) : "memory");
    }
    __syncthreads();

    // Reduce the 32 lane-copies of bin t (rotated start -> conflict-free),
    // one spread-address global RED per bin.
    {
        const unsigned t = threadIdx.x;
        unsigned int s = 0;
        #pragma unroll
        for (int c = 0; c < 32; c++) s += sh[t * 32 + ((c + t) & 31u)];
        atomicAdd(&g_hist[(unsigned)b * LEVELS + t], s);
    }

    // ---- Phase 2: row-completion sync ----
    __threadfence();                 // publish this thread's REDG
    __syncthreads();                 // all threads of CTA published
    if (threadIdx.x == 0) {
        unsigned t = atomicAdd(&g_cnt[b], 1u);
        if (t == BPR - 1) atomicExch(&g_flag[b], 1u);   // release row
        while (*(volatile unsigned*)&g_flag[b] == 0u) __nanosleep(64);
    }
    __syncthreads();
    __threadfence();                 // acquire: g_hist row now complete

    // ---- Phase 3: broadcast bins [i*32, i*32+32) of row b ----
    float* shf = (float*)sh;         // reuse smem
    const unsigned binBase = (unsigned)b * LEVELS + (unsigned)i * 32u;
    if (threadIdx.x < 32)
        shf[threadIdx.x] = (float)g_hist[binBase + threadIdx.x];
    __syncthreads();

    float4* __restrict__ dst =
        out + ((size_t)b * LEVELS + (size_t)i * 32u) * (LEVELS / 4);
    #pragma unroll
    for (int k = threadIdx.x; k < 32 * (LEVELS / 4); k += HTHREADS) {
        float v = shf[k >> 6];
        dst[k] = make_float4(v, v, v, v);
    }

    // reset this CTA's own g_hist entries (sole reader was this CTA)
    if (threadIdx.x < 32) g_hist[binBase + threadIdx.x] = 0u;

    // last CTA of the row to finish resets the row's sync state
    if (threadIdx.x == 0) {
        __threadfence();
        unsigned d = atomicAdd(&g_done[b], 1u);
        if (d == BPR - 1) {
            g_cnt[b]  = 0u;
            g_flag[b] = 0u;
            g_done[b] = 0u;
            __threadfence();
        }
    }
}

// ---------------------------------------------------------------------------
extern "C" void kernel_launch(void* const* d_in, const int* in_sizes, int n_in,
                              void* d_out, int out_size) {
    const int4* x = (const int4*)d_in[0];
    float4* out = (float4*)d_out;

    dim3 grid(BPR, BATCH);
    fused_kernel<<<grid, HTHREADS>>>(x, out);
}